// round 1
// baseline (speedup 1.0000x reference)
#include <cuda_runtime.h>
#include <cstdint>
#include <math.h>

// SpatialGlimpse: B=64 images [512,512,3] f32, offsets [64,2].
// out[b,i,j,c*3+d] for d in {0,1,2}, k=2^d: separable (k+1)x(k+1) stencil
// (bilinear weights are constant per batch since the sample grid has unit spacing).

static constexpr int BATCH  = 64;
static constexpr int H = 512, W = 512, C = 3;
static constexpr int OUTHW  = 64;
static constexpr int NDEPTH = 3;
static constexpr int ROWFL  = W * C;   // 1536 floats per image row
static constexpr int NT     = 256;     // threads per block

template<int K> struct Cfg;
template<> struct Cfg<1> { static constexpr int TILE_I = 16; static constexpr int ROWF = 204; static constexpr int NV = 3; };
template<> struct Cfg<2> { static constexpr int TILE_I = 8;  static constexpr int ROWF = 396; static constexpr int NV = 3; };
template<> struct Cfg<4> { static constexpr int TILE_I = 4;  static constexpr int ROWF = 780; static constexpr int NV = 5; };
// ROWF >= 3*(64K+1) + 6 (alignment slack both ends), multiple of 4 for 16B row alignment.
// IR = TILE_I*K + 1 = 17 input rows for every depth.

__device__ __forceinline__ uint32_t smem_u32(const void* p) {
    return (uint32_t)__cvta_generic_to_shared(p);
}
__device__ __forceinline__ void mbar_init(uint32_t a, uint32_t cnt) {
    asm volatile("mbarrier.init.shared.b64 [%0], %1;" :: "r"(a), "r"(cnt) : "memory");
}
__device__ __forceinline__ void mbar_expect_tx(uint32_t a, uint32_t bytes) {
    asm volatile("mbarrier.arrive.expect_tx.shared.b64 _, [%0], %1;" :: "r"(a), "r"(bytes) : "memory");
}
__device__ __forceinline__ void mbar_wait(uint32_t a, uint32_t parity) {
    asm volatile(
        "{\n\t"
        ".reg .pred P;\n\t"
        "LAB_WAIT_%=:\n\t"
        "mbarrier.try_wait.parity.acquire.cta.shared::cta.b64 P, [%0], %1, 0x989680;\n\t"
        "@P bra LAB_DONE_%=;\n\t"
        "bra LAB_WAIT_%=;\n\t"
        "LAB_DONE_%=:\n\t"
        "}"
        :: "r"(a), "r"(parity) : "memory");
}
__device__ __forceinline__ void bulk_g2s(uint32_t dst, const void* src, uint32_t bytes, uint32_t mbar) {
    asm volatile(
        "cp.async.bulk.shared::cluster.global.mbarrier::complete_tx::bytes [%0], [%1], %2, [%3];"
        :: "r"(dst), "l"(src), "r"(bytes), "r"(mbar) : "memory");
}

// Compute one output pixel (3 channels) from the SMEM tile.
// SH = (runtime byte-shift within float4) as a template param so every v[] index
// is compile-time constant (keeps the window array in registers).
template<int K, int SH>
__device__ __forceinline__ void compute_one(
    const float* __restrict__ tile, int rowbase, int a0,
    float wx, float wy, float& o0, float& o1, float& o2)
{
    constexpr int RF = Cfg<K>::ROWF;
    constexpr int NV = Cfg<K>::NV;
    const float hx0 = 1.0f - wx;
    float acc0 = 0.f, acc1 = 0.f, acc2 = 0.f;
#pragma unroll
    for (int p = 0; p <= K; p++) {
        const float4* rp = reinterpret_cast<const float4*>(tile + (rowbase + p) * RF + a0);
        float v[4 * NV];
#pragma unroll
        for (int t = 0; t < NV; t++) {
            float4 q = rp[t];
            v[4*t+0] = q.x; v[4*t+1] = q.y; v[4*t+2] = q.z; v[4*t+3] = q.w;
        }
        float vw = (p == 0) ? (1.0f - wy) : ((p == K) ? wy : 1.0f);
        float r0 = hx0 * v[SH + 0] + wx * v[SH + 3*K + 0];
        float r1 = hx0 * v[SH + 1] + wx * v[SH + 3*K + 1];
        float r2 = hx0 * v[SH + 2] + wx * v[SH + 3*K + 2];
#pragma unroll
        for (int q = 1; q < K; q++) {
            r0 += v[SH + 3*q + 0];
            r1 += v[SH + 3*q + 1];
            r2 += v[SH + 3*q + 2];
        }
        acc0 += vw * r0; acc1 += vw * r1; acc2 += vw * r2;
    }
    o0 = acc0; o1 = acc1; o2 = acc2;
}

template<int K, int D>
__global__ __launch_bounds__(NT)
void glimpse_kernel(const float* __restrict__ img, const float* __restrict__ offs,
                    float* __restrict__ out)
{
    constexpr int TILE_I = Cfg<K>::TILE_I;
    constexpr int RF     = Cfg<K>::ROWF;
    constexpr int IR     = TILE_I * K + 1;      // 17
    constexpr int SPAN   = OUTHW * K + 1;       // input pixel span across x

    extern __shared__ float smem[];
    float* tile = smem + 4;                     // 16B offset; [0..15] holds the mbarrier
    const uint32_t mbar = smem_u32(smem);

    const int b   = blockIdx.y;
    const int i0  = blockIdx.x * TILE_I;
    const int tid = threadIdx.x;

    // Per-batch geometry (fp32 ops chosen to round identically to the reference lattice)
    const float cy = (offs[2*b + 0] + 1.0f) * (H * 0.5f);
    const float cx = (offs[2*b + 1] + 1.0f) * (W * 0.5f);
    const float Ey = cy - (OUTHW * K - 1) * 0.5f;   // exact subtraction (Sterbenz-range)
    const float Ex = cx - (OUTHW * K - 1) * 0.5f;
    const int   y0 = (int)floorf(Ey);
    const int   x0 = (int)floorf(Ex);
    const float wy = Ey - (float)y0;
    const float wx = Ex - (float)x0;

    // Row staging window [start_f, end_f) in floats, 16B-aligned both ends, clipped to the image row.
    const int x_hi   = min(x0 + SPAN, W);
    const int start_f = (x0 * 3) & ~3;
    const int end_f   = min((x_hi * 3 + 3) & ~3, ROWFL);
    const int validf  = end_f - start_f;
    const int off0    = x0 * 3 - start_f;       // 0..3
    const int rowbytes = validf * 4;            // multiple of 16
    const int ytop    = y0 + i0 * K;

    if (tid == 0) {
        mbar_init(mbar, 1);
        asm volatile("fence.proxy.async.shared::cta;" ::: "memory");
    }
    __syncthreads();

    if (tid == 0) {
        int nvalid = 0;
#pragma unroll
        for (int r = 0; r < IR; r++) if (ytop + r < H) nvalid++;
        mbar_expect_tx(mbar, (uint32_t)(nvalid * rowbytes));
#pragma unroll
        for (int r = 0; r < IR; r++) {
            const int gy = ytop + r;
            if (gy < H) {
                const float* src = img + ((size_t)b * H + gy) * ROWFL + start_f;
                bulk_g2s(smem_u32(tile + r * RF), src, (uint32_t)rowbytes, mbar);
            }
        }
    }

    // Zero the tails (disjoint from bulk-copy destination bytes) and any y>=H rows.
    {
        const int ntail = RF - validf;          // >= 3 always
        for (int idx = tid; idx < IR * ntail; idx += NT) {
            const int r = idx / ntail;
            tile[r * RF + validf + idx % ntail] = 0.0f;
        }
#pragma unroll
        for (int r = 0; r < IR; r++) {
            if (ytop + r >= H) {
                for (int f = tid; f < validf; f += NT) tile[r * RF + f] = 0.0f;
            }
        }
    }

    mbar_wait(mbar, 0);
    __syncthreads();

    constexpr float inv = 1.0f / (K * K);
    constexpr int OUTS = (TILE_I * OUTHW) / NT;
#pragma unroll
    for (int s = 0; s < OUTS; s++) {
        const int ti = (tid >> 6) + s * (NT / OUTHW);
        const int j  = tid & (OUTHW - 1);
        const int sidx = off0 + 3 * K * j;
        const int a0   = sidx & ~3;
        float o0, o1, o2;
        switch (sidx & 3) {
        case 0:  compute_one<K,0>(tile, ti*K, a0, wx, wy, o0, o1, o2); break;
        case 1:  compute_one<K,1>(tile, ti*K, a0, wx, wy, o0, o1, o2); break;
        case 2:  compute_one<K,2>(tile, ti*K, a0, wx, wy, o0, o1, o2); break;
        default: compute_one<K,3>(tile, ti*K, a0, wx, wy, o0, o1, o2); break;
        }
        const size_t ob = (((size_t)b * OUTHW + (i0 + ti)) * OUTHW + j) * (C * NDEPTH);
        out[ob + 0 * NDEPTH + D] = o0 * inv;
        out[ob + 1 * NDEPTH + D] = o1 * inv;
        out[ob + 2 * NDEPTH + D] = o2 * inv;
    }
}

extern "C" void kernel_launch(void* const* d_in, const int* in_sizes, int n_in,
                              void* d_out, int out_size)
{
    (void)in_sizes; (void)n_in; (void)out_size;
    const float* img  = (const float*)d_in[0];
    const float* offs = (const float*)d_in[1];
    float* out = (float*)d_out;

    const int smem0 = 16 + 17 * Cfg<1>::ROWF * 4;   // 13888
    const int smem1 = 16 + 17 * Cfg<2>::ROWF * 4;   // 26944
    const int smem2 = 16 + 17 * Cfg<4>::ROWF * 4;   // 53056

    cudaFuncSetAttribute(glimpse_kernel<1,0>, cudaFuncAttributeMaxDynamicSharedMemorySize, smem0);
    cudaFuncSetAttribute(glimpse_kernel<2,1>, cudaFuncAttributeMaxDynamicSharedMemorySize, smem1);
    cudaFuncSetAttribute(glimpse_kernel<4,2>, cudaFuncAttributeMaxDynamicSharedMemorySize, smem2);

    glimpse_kernel<1,0><<<dim3(OUTHW / Cfg<1>::TILE_I, BATCH), NT, smem0>>>(img, offs, out);
    glimpse_kernel<2,1><<<dim3(OUTHW / Cfg<2>::TILE_I, BATCH), NT, smem1>>>(img, offs, out);
    glimpse_kernel<4,2><<<dim3(OUTHW / Cfg<4>::TILE_I, BATCH), NT, smem2>>>(img, offs, out);
}

// round 2
// speedup vs baseline: 1.2018x; 1.2018x over previous
#include <cuda_runtime.h>
#include <cstdint>
#include <math.h>

// SpatialGlimpse fused: B=64 images [512,512,3] f32, offsets [64,2].
// out[b,i,j,c*3+d], d in {0,1,2}, k=2^d: separable (k+1)x(k+1) stencil
// (bilinear weights are constant per batch since the sample grid has unit spacing).
// R2: single fused launch (1792 blocks), K=4 region scheduled first.

static constexpr int BATCH  = 64;
static constexpr int H = 512, W = 512, C = 3;
static constexpr int OUTHW  = 64;
static constexpr int NDEPTH = 3;
static constexpr int ROWFL  = W * C;   // 1536 floats per image row
static constexpr int NT     = 256;     // threads per block

template<int K> struct Cfg;
template<> struct Cfg<1> { static constexpr int TILE_I = 16; static constexpr int ROWF = 204; static constexpr int NV = 3; };
template<> struct Cfg<2> { static constexpr int TILE_I = 8;  static constexpr int ROWF = 396; static constexpr int NV = 3; };
template<> struct Cfg<4> { static constexpr int TILE_I = 4;  static constexpr int ROWF = 780; static constexpr int NV = 5; };
// IR = TILE_I*K + 1 = 17 input rows for every depth.

// Fused grid layout: [0,1024) -> K=4, [1024,1536) -> K=2, [1536,1792) -> K=1.
static constexpr int NBLK4 = BATCH * (OUTHW / Cfg<4>::TILE_I);   // 1024
static constexpr int NBLK2 = BATCH * (OUTHW / Cfg<2>::TILE_I);   // 512
static constexpr int NBLK1 = BATCH * (OUTHW / Cfg<1>::TILE_I);   // 256
static constexpr int NBLK  = NBLK4 + NBLK2 + NBLK1;              // 1792

static constexpr int SMEM_MAX = 16 + 17 * Cfg<4>::ROWF * 4;      // 53056

__device__ __forceinline__ uint32_t smem_u32(const void* p) {
    return (uint32_t)__cvta_generic_to_shared(p);
}
__device__ __forceinline__ void mbar_init(uint32_t a, uint32_t cnt) {
    asm volatile("mbarrier.init.shared.b64 [%0], %1;" :: "r"(a), "r"(cnt) : "memory");
}
__device__ __forceinline__ void mbar_expect_tx(uint32_t a, uint32_t bytes) {
    asm volatile("mbarrier.arrive.expect_tx.shared.b64 _, [%0], %1;" :: "r"(a), "r"(bytes) : "memory");
}
__device__ __forceinline__ void mbar_wait(uint32_t a, uint32_t parity) {
    asm volatile(
        "{\n\t"
        ".reg .pred P;\n\t"
        "LAB_WAIT_%=:\n\t"
        "mbarrier.try_wait.parity.acquire.cta.shared::cta.b64 P, [%0], %1, 0x989680;\n\t"
        "@P bra LAB_DONE_%=;\n\t"
        "bra LAB_WAIT_%=;\n\t"
        "LAB_DONE_%=:\n\t"
        "}"
        :: "r"(a), "r"(parity) : "memory");
}
__device__ __forceinline__ void bulk_g2s(uint32_t dst, const void* src, uint32_t bytes, uint32_t mbar) {
    asm volatile(
        "cp.async.bulk.shared::cluster.global.mbarrier::complete_tx::bytes [%0], [%1], %2, [%3];"
        :: "r"(dst), "l"(src), "r"(bytes), "r"(mbar) : "memory");
}

// Compute one output pixel (3 channels) from the SMEM tile.
// SH = sub-float4 shift as a template param so all v[] indices are compile-time
// (keeps the window array in registers).
template<int K, int SH>
__device__ __forceinline__ void compute_one(
    const float* __restrict__ tile, int rowbase, int a0,
    float wx, float wy, float& o0, float& o1, float& o2)
{
    constexpr int RF = Cfg<K>::ROWF;
    constexpr int NV = Cfg<K>::NV;
    const float hx0 = 1.0f - wx;
    float acc0 = 0.f, acc1 = 0.f, acc2 = 0.f;
#pragma unroll
    for (int p = 0; p <= K; p++) {
        const float4* rp = reinterpret_cast<const float4*>(tile + (rowbase + p) * RF + a0);
        float v[4 * NV];
#pragma unroll
        for (int t = 0; t < NV; t++) {
            float4 q = rp[t];
            v[4*t+0] = q.x; v[4*t+1] = q.y; v[4*t+2] = q.z; v[4*t+3] = q.w;
        }
        float vw = (p == 0) ? (1.0f - wy) : ((p == K) ? wy : 1.0f);
        float r0 = hx0 * v[SH + 0] + wx * v[SH + 3*K + 0];
        float r1 = hx0 * v[SH + 1] + wx * v[SH + 3*K + 1];
        float r2 = hx0 * v[SH + 2] + wx * v[SH + 3*K + 2];
#pragma unroll
        for (int q = 1; q < K; q++) {
            r0 += v[SH + 3*q + 0];
            r1 += v[SH + 3*q + 1];
            r2 += v[SH + 3*q + 2];
        }
        acc0 += vw * r0; acc1 += vw * r1; acc2 += vw * r2;
    }
    o0 = acc0; o1 = acc1; o2 = acc2;
}

template<int K, int D>
__device__ __forceinline__ void glimpse_body(
    const float* __restrict__ img, const float* __restrict__ offs,
    float* __restrict__ out, float* smem, int b, int i0)
{
    constexpr int TILE_I = Cfg<K>::TILE_I;
    constexpr int RF     = Cfg<K>::ROWF;
    constexpr int IR     = TILE_I * K + 1;      // 17
    constexpr int SPAN   = OUTHW * K + 1;       // input pixel span across x

    float* tile = smem + 4;                     // 16B offset; smem[0..3] holds the mbarrier
    const uint32_t mbar = smem_u32(smem);
    const int tid = threadIdx.x;

    // Per-batch geometry (fp32 ops round identically to the reference lattice)
    const float cy = (offs[2*b + 0] + 1.0f) * (H * 0.5f);
    const float cx = (offs[2*b + 1] + 1.0f) * (W * 0.5f);
    const float Ey = cy - (OUTHW * K - 1) * 0.5f;
    const float Ex = cx - (OUTHW * K - 1) * 0.5f;
    const int   y0 = (int)floorf(Ey);
    const int   x0 = (int)floorf(Ex);
    const float wy = Ey - (float)y0;
    const float wx = Ex - (float)x0;

    // Row staging window [start_f, end_f) in floats, 16B-aligned both ends, clipped to the image row.
    const int x_hi    = min(x0 + SPAN, W);
    const int start_f = (x0 * 3) & ~3;
    const int end_f   = min((x_hi * 3 + 3) & ~3, ROWFL);
    const int validf  = end_f - start_f;
    const int off0    = x0 * 3 - start_f;       // 0..3
    const int rowbytes = validf * 4;            // multiple of 16
    const int ytop    = y0 + i0 * K;

    if (tid == 0) {
        mbar_init(mbar, 1);
        asm volatile("fence.proxy.async.shared::cta;" ::: "memory");
    }
    __syncthreads();

    if (tid == 0) {
        int nvalid = 0;
#pragma unroll
        for (int r = 0; r < IR; r++) if (ytop + r < H) nvalid++;
        mbar_expect_tx(mbar, (uint32_t)(nvalid * rowbytes));
#pragma unroll
        for (int r = 0; r < IR; r++) {
            const int gy = ytop + r;
            if (gy < H) {
                const float* src = img + ((size_t)b * H + gy) * ROWFL + start_f;
                bulk_g2s(smem_u32(tile + r * RF), src, (uint32_t)rowbytes, mbar);
            }
        }
    }

    // Zero the tails (disjoint from bulk-copy destination bytes) and any y>=H rows.
    {
        const int ntail = RF - validf;          // >= 3 always
        for (int idx = tid; idx < IR * ntail; idx += NT) {
            const int r = idx / ntail;
            tile[r * RF + validf + idx % ntail] = 0.0f;
        }
#pragma unroll
        for (int r = 0; r < IR; r++) {
            if (ytop + r >= H) {
                for (int f = tid; f < validf; f += NT) tile[r * RF + f] = 0.0f;
            }
        }
    }

    mbar_wait(mbar, 0);
    __syncthreads();

    constexpr float inv = 1.0f / (K * K);
    constexpr int OUTS = (TILE_I * OUTHW) / NT;
#pragma unroll
    for (int s = 0; s < OUTS; s++) {
        const int ti = (tid >> 6) + s * (NT / OUTHW);
        const int j  = tid & (OUTHW - 1);
        const int sidx = off0 + 3 * K * j;
        const int a0   = sidx & ~3;
        float o0, o1, o2;
        switch (sidx & 3) {
        case 0:  compute_one<K,0>(tile, ti*K, a0, wx, wy, o0, o1, o2); break;
        case 1:  compute_one<K,1>(tile, ti*K, a0, wx, wy, o0, o1, o2); break;
        case 2:  compute_one<K,2>(tile, ti*K, a0, wx, wy, o0, o1, o2); break;
        default: compute_one<K,3>(tile, ti*K, a0, wx, wy, o0, o1, o2); break;
        }
        const size_t ob = (((size_t)b * OUTHW + (i0 + ti)) * OUTHW + j) * (C * NDEPTH);
        out[ob + 0 * NDEPTH + D] = o0 * inv;
        out[ob + 1 * NDEPTH + D] = o1 * inv;
        out[ob + 2 * NDEPTH + D] = o2 * inv;
    }
}

__global__ __launch_bounds__(NT)
void glimpse_fused(const float* __restrict__ img, const float* __restrict__ offs,
                   float* __restrict__ out)
{
    extern __shared__ float smem[];
    const int bid = blockIdx.x;
    // Longest-running region (K=4) first for better wave packing.
    if (bid < NBLK4) {
        glimpse_body<4, 2>(img, offs, out, smem, bid >> 4, (bid & 15) * Cfg<4>::TILE_I);
    } else if (bid < NBLK4 + NBLK2) {
        const int r = bid - NBLK4;
        glimpse_body<2, 1>(img, offs, out, smem, r >> 3, (r & 7) * Cfg<2>::TILE_I);
    } else {
        const int r = bid - (NBLK4 + NBLK2);
        glimpse_body<1, 0>(img, offs, out, smem, r >> 2, (r & 3) * Cfg<1>::TILE_I);
    }
}

extern "C" void kernel_launch(void* const* d_in, const int* in_sizes, int n_in,
                              void* d_out, int out_size)
{
    (void)in_sizes; (void)n_in; (void)out_size;
    const float* img  = (const float*)d_in[0];
    const float* offs = (const float*)d_in[1];
    float* out = (float*)d_out;

    cudaFuncSetAttribute(glimpse_fused, cudaFuncAttributeMaxDynamicSharedMemorySize, SMEM_MAX);
    glimpse_fused<<<NBLK, NT, SMEM_MAX>>>(img, offs, out);
}

// round 3
// speedup vs baseline: 1.3322x; 1.1085x over previous
#include <cuda_runtime.h>
#include <cstdint>
#include <math.h>

// SpatialGlimpse fused, two-phase separable stencil.
// Phase A: horizontal (K+1)-tap weighted sums, one thread per (row, j) -> hs[] (float4).
//          Lane stride = 12 words for every K => conflict-free LDS.128.
// Phase B: vertical (K+1)-tap weighted sum over hs, consecutive-j float4 => conflict-free.

static constexpr int BATCH  = 64;
static constexpr int H = 512, W = 512, C = 3;
static constexpr int OUTHW  = 64;
static constexpr int NDEPTH = 3;
static constexpr int ROWFL  = W * C;   // 1536 floats per image row
static constexpr int NT     = 256;

template<int K> struct Cfg;
template<> struct Cfg<1> { static constexpr int TILE_I = 8; static constexpr int ROWF = 204; static constexpr int NV = 3; };
template<> struct Cfg<2> { static constexpr int TILE_I = 4; static constexpr int ROWF = 396; static constexpr int NV = 3; };
template<> struct Cfg<4> { static constexpr int TILE_I = 2; static constexpr int ROWF = 780; static constexpr int NV = 5; };
// IR = TILE_I*K + 1 = 9 input rows for every depth.

static constexpr int NBLK4 = BATCH * (OUTHW / Cfg<4>::TILE_I);   // 2048
static constexpr int NBLK2 = BATCH * (OUTHW / Cfg<2>::TILE_I);   // 1024
static constexpr int NBLK1 = BATCH * (OUTHW / Cfg<1>::TILE_I);   // 512
static constexpr int NBLK  = NBLK4 + NBLK2 + NBLK1;              // 3584

// SMEM: [0,16) mbar | tile IR*ROWF floats | hs IR*64 float4
static constexpr int SMEM_MAX = 16 + 9 * Cfg<4>::ROWF * 4 + 9 * OUTHW * 16;  // 37312

__device__ __forceinline__ uint32_t smem_u32(const void* p) {
    return (uint32_t)__cvta_generic_to_shared(p);
}
__device__ __forceinline__ void mbar_init(uint32_t a, uint32_t cnt) {
    asm volatile("mbarrier.init.shared.b64 [%0], %1;" :: "r"(a), "r"(cnt) : "memory");
}
__device__ __forceinline__ void mbar_expect_tx(uint32_t a, uint32_t bytes) {
    asm volatile("mbarrier.arrive.expect_tx.shared.b64 _, [%0], %1;" :: "r"(a), "r"(bytes) : "memory");
}
__device__ __forceinline__ void mbar_wait(uint32_t a, uint32_t parity) {
    asm volatile(
        "{\n\t"
        ".reg .pred P;\n\t"
        "LAB_WAIT_%=:\n\t"
        "mbarrier.try_wait.parity.acquire.cta.shared::cta.b64 P, [%0], %1, 0x989680;\n\t"
        "@P bra LAB_DONE_%=;\n\t"
        "bra LAB_WAIT_%=;\n\t"
        "LAB_DONE_%=:\n\t"
        "}"
        :: "r"(a), "r"(parity) : "memory");
}
__device__ __forceinline__ void bulk_g2s(uint32_t dst, const void* src, uint32_t bytes, uint32_t mbar) {
    asm volatile(
        "cp.async.bulk.shared::cluster.global.mbarrier::complete_tx::bytes [%0], [%1], %2, [%3];"
        :: "r"(dst), "l"(src), "r"(bytes), "r"(mbar) : "memory");
}

// Horizontal weighted sum for one (row, j): h.{x,y,z} over window of K+1 pixels.
// SH = sub-float4 shift (compile-time so v[] stays in registers).
template<int K, int SH>
__device__ __forceinline__ void hreduce_one(const float* __restrict__ rowp, float wx, float4& h)
{
    constexpr int NV = Cfg<K>::NV;
    const float hx0 = 1.0f - wx;
    float v[4 * NV];
    const float4* rp = reinterpret_cast<const float4*>(rowp);
#pragma unroll
    for (int t = 0; t < NV; t++) {
        float4 q = rp[t];
        v[4*t+0] = q.x; v[4*t+1] = q.y; v[4*t+2] = q.z; v[4*t+3] = q.w;
    }
    float r0 = hx0 * v[SH + 0] + wx * v[SH + 3*K + 0];
    float r1 = hx0 * v[SH + 1] + wx * v[SH + 3*K + 1];
    float r2 = hx0 * v[SH + 2] + wx * v[SH + 3*K + 2];
#pragma unroll
    for (int q = 1; q < K; q++) {
        r0 += v[SH + 3*q + 0];
        r1 += v[SH + 3*q + 1];
        r2 += v[SH + 3*q + 2];
    }
    h.x = r0; h.y = r1; h.z = r2; h.w = 0.0f;
}

template<int K, int D>
__device__ __forceinline__ void glimpse_body(
    const float* __restrict__ img, const float* __restrict__ offs,
    float* __restrict__ out, float* smem, int b, int i0)
{
    constexpr int TILE_I = Cfg<K>::TILE_I;
    constexpr int RF     = Cfg<K>::ROWF;
    constexpr int IR     = TILE_I * K + 1;      // 9
    constexpr int SPAN   = OUTHW * K + 1;

    float* tile = smem + 4;                     // smem[0..3] holds the mbarrier
    float4* hs  = reinterpret_cast<float4*>(smem + 4 + IR * RF);
    const uint32_t mbar = smem_u32(smem);
    const int tid = threadIdx.x;

    // Per-batch geometry (fp32 ops round identically to the reference lattice)
    const float cy = (offs[2*b + 0] + 1.0f) * (H * 0.5f);
    const float cx = (offs[2*b + 1] + 1.0f) * (W * 0.5f);
    const float Ey = cy - (OUTHW * K - 1) * 0.5f;
    const float Ex = cx - (OUTHW * K - 1) * 0.5f;
    const int   y0 = (int)floorf(Ey);
    const int   x0 = (int)floorf(Ex);
    const float wy = Ey - (float)y0;
    const float wx = Ex - (float)x0;

    // Row staging window [start_f, end_f), 16B-aligned both ends, clipped to the image row.
    const int x_hi    = min(x0 + SPAN, W);
    const int start_f = (x0 * 3) & ~3;
    const int end_f   = min((x_hi * 3 + 3) & ~3, ROWFL);
    const int validf  = end_f - start_f;
    const int off0    = x0 * 3 - start_f;       // 0..3
    const int rowbytes = validf * 4;            // multiple of 16
    const int ytop    = y0 + i0 * K;

    if (tid == 0) {
        mbar_init(mbar, 1);
        asm volatile("fence.proxy.async.shared::cta;" ::: "memory");
    }
    __syncthreads();

    if (tid == 0) {
        int nvalid = 0;
#pragma unroll
        for (int r = 0; r < IR; r++) if (ytop + r < H) nvalid++;
        mbar_expect_tx(mbar, (uint32_t)(nvalid * rowbytes));
#pragma unroll
        for (int r = 0; r < IR; r++) {
            const int gy = ytop + r;
            if (gy < H) {
                const float* src = img + ((size_t)b * H + gy) * ROWFL + start_f;
                bulk_g2s(smem_u32(tile + r * RF), src, (uint32_t)rowbytes, mbar);
            }
        }
    }

    // Zero tails (disjoint from bulk-copy bytes) and any y>=H rows.
    {
        const int ntail = RF - validf;
        for (int idx = tid; idx < IR * ntail; idx += NT) {
            const int r = idx / ntail;
            tile[r * RF + validf + idx % ntail] = 0.0f;
        }
#pragma unroll
        for (int r = 0; r < IR; r++) {
            if (ytop + r >= H) {
                for (int f = tid; f < validf; f += NT) tile[r * RF + f] = 0.0f;
            }
        }
    }

    mbar_wait(mbar, 0);
    __syncthreads();

    // ── Phase A: horizontal reduction, one thread per (row, j). Conflict-free. ──
    {
        const int j = tid & 63;
        const int sidx = off0 + 3 * K * j;
        const int a0   = sidx & ~3;
        const int sh   = sidx & 3;
#pragma unroll
        for (int r0 = 0; r0 < IR; r0 += NT / 64) {
            const int r = r0 + (tid >> 6);
            if (r < IR) {
                const float* rowp = tile + r * RF + a0;
                float4 h;
                switch (sh) {
                case 0:  hreduce_one<K,0>(rowp, wx, h); break;
                case 1:  hreduce_one<K,1>(rowp, wx, h); break;
                case 2:  hreduce_one<K,2>(rowp, wx, h); break;
                default: hreduce_one<K,3>(rowp, wx, h); break;
                }
                hs[r * 64 + j] = h;
            }
        }
    }
    __syncthreads();

    // ── Phase B: vertical reduction over hs. Conflict-free. ──
    constexpr float inv = 1.0f / (K * K);
    constexpr int NOUT = TILE_I * OUTHW;
    const float wy0 = 1.0f - wy;
    for (int o = tid; o < NOUT; o += NT) {
        const int ti = o >> 6;
        const int j  = o & 63;
        float4 a = hs[(ti * K) * 64 + j];
        float o0 = wy0 * a.x, o1 = wy0 * a.y, o2 = wy0 * a.z;
#pragma unroll
        for (int p = 1; p < K; p++) {
            float4 m = hs[(ti * K + p) * 64 + j];
            o0 += m.x; o1 += m.y; o2 += m.z;
        }
        float4 e = hs[(ti * K + K) * 64 + j];
        o0 += wy * e.x; o1 += wy * e.y; o2 += wy * e.z;

        const size_t ob = (((size_t)b * OUTHW + (i0 + ti)) * OUTHW + j) * (C * NDEPTH);
        out[ob + 0 * NDEPTH + D] = o0 * inv;
        out[ob + 1 * NDEPTH + D] = o1 * inv;
        out[ob + 2 * NDEPTH + D] = o2 * inv;
    }
}

__global__ __launch_bounds__(NT)
void glimpse_fused(const float* __restrict__ img, const float* __restrict__ offs,
                   float* __restrict__ out)
{
    extern __shared__ float smem[];
    const int bid = blockIdx.x;
    if (bid < NBLK4) {                                   // K=4: 32 blocks/image
        glimpse_body<4, 2>(img, offs, out, smem, bid >> 5, (bid & 31) * Cfg<4>::TILE_I);
    } else if (bid < NBLK4 + NBLK2) {                    // K=2: 16 blocks/image
        const int r = bid - NBLK4;
        glimpse_body<2, 1>(img, offs, out, smem, r >> 4, (r & 15) * Cfg<2>::TILE_I);
    } else {                                             // K=1: 8 blocks/image
        const int r = bid - (NBLK4 + NBLK2);
        glimpse_body<1, 0>(img, offs, out, smem, r >> 3, (r & 7) * Cfg<1>::TILE_I);
    }
}

extern "C" void kernel_launch(void* const* d_in, const int* in_sizes, int n_in,
                              void* d_out, int out_size)
{
    (void)in_sizes; (void)n_in; (void)out_size;
    const float* img  = (const float*)d_in[0];
    const float* offs = (const float*)d_in[1];
    float* out = (float*)d_out;

    cudaFuncSetAttribute(glimpse_fused, cudaFuncAttributeMaxDynamicSharedMemorySize, SMEM_MAX);
    glimpse_fused<<<NBLK, NT, SMEM_MAX>>>(img, offs, out);
}